// round 1
// baseline (speedup 1.0000x reference)
#include <cuda_runtime.h>
#include <cuda_bf16.h>

// ConvTreeBlock: N=1e6 nodes, C=16 channels, KS=9 neighbors.
//   y1 = gather(data) (*) w1 + b1          [conv over 9 gathered rows]
//   h  = leaky(BN1(y1))                    [BN = training-mode batch stats]
//   y2 = gather(h) (*) w2
//   out= leaky(BN2(y2) + data)
//
// 7 launches on one stream (graph-capture-safe, dependency via stream order):
//   zero_stats -> conv1 -> stats1 -> bnact1 -> conv2 -> stats2 -> bnact2(final)
//
// Scratch in __device__ globals (no runtime allocation).

#define NMAX 1000000
#define CMAX 16

__device__ float g_y1[(size_t)NMAX * CMAX];   // raw conv1 output
__device__ float g_h [(size_t)NMAX * CMAX];   // leaky(BN1(y1))
__device__ float g_stats[64];                  // [0:16]sum1 [16:32]ssq1 [32:48]sum2 [48:64]ssq2

static constexpr float EPS   = 1e-5f;
static constexpr float SLOPE = 0.2f;

__global__ void k_zero_stats()
{
    if (threadIdx.x < 64) g_stats[threadIdx.x] = 0.0f;
}

// One node per thread. Weights pre-transposed into smem as ws[(j*16+c)*16 + o]
// so the innermost o-loop reads contiguous 64B rows (LDS.128, broadcast).
// LAYER=1: src=data(param), dst=g_y1, bias added. LAYER=2: src=g_h, dst=param, no bias.
template<int LAYER>
__global__ __launch_bounds__(256)
void k_conv(const float* __restrict__ src_param,
            const int*   __restrict__ ind,
            const float* __restrict__ w,      // [c][o][j] = c*144 + o*9 + j
            const float* __restrict__ bias,   // only LAYER==1
            float*       __restrict__ dst_param,
            int n)
{
    __shared__ float ws[2304];
    for (int s = threadIdx.x; s < 2304; s += 256) {
        int o = s & 15, kk = s >> 4;
        int c = kk & 15, j = kk >> 4;
        ws[s] = w[c * 144 + o * 9 + j];
    }
    __syncthreads();

    int node = blockIdx.x * 256 + threadIdx.x;
    if (node >= n) return;

    const float* src = (LAYER == 1) ? src_param : g_h;
    float*       dst = (LAYER == 1) ? g_y1      : dst_param;

    int nj[9];
#pragma unroll
    for (int j = 0; j < 9; ++j) nj[j] = ind[(size_t)node * 9 + j];

    float acc[16];
#pragma unroll
    for (int o = 0; o < 16; ++o) acc[o] = (LAYER == 1) ? bias[o] : 0.0f;

#pragma unroll 1   // keep body small (I$ L0) ; 4x LDG.128 MLP per iter, warps hide L2 latency
    for (int j = 0; j < 9; ++j) {
        const float4* r = reinterpret_cast<const float4*>(src + (size_t)nj[j] * 16);
        float4 v0 = r[0], v1 = r[1], v2 = r[2], v3 = r[3];
        float xv[16] = {v0.x, v0.y, v0.z, v0.w,
                        v1.x, v1.y, v1.z, v1.w,
                        v2.x, v2.y, v2.z, v2.w,
                        v3.x, v3.y, v3.z, v3.w};
        const float* wj = ws + j * 256;
#pragma unroll
        for (int c = 0; c < 16; ++c) {
            float x = xv[c];
#pragma unroll
            for (int o = 0; o < 16; ++o)
                acc[o] = fmaf(x, wj[c * 16 + o], acc[o]);
        }
    }

    float4* out4 = reinterpret_cast<float4*>(dst + (size_t)node * 16);
    out4[0] = make_float4(acc[0],  acc[1],  acc[2],  acc[3]);
    out4[1] = make_float4(acc[4],  acc[5],  acc[6],  acc[7]);
    out4[2] = make_float4(acc[8],  acc[9],  acc[10], acc[11]);
    out4[3] = make_float4(acc[12], acc[13], acc[14], acc[15]);
}

// Per-channel sum/sumsq. Each thread's float4 covers a FIXED 4-channel group
// (stride is a multiple of 16 floats), so local fp32 partials + xor-shuffle
// reduce over lanes sharing lane%4, then 8 global atomics from lanes 0..3.
// X: 1 -> g_y1, 2 -> x_param (d_out).
template<int X>
__global__ __launch_bounds__(256)
void k_stats(const float* __restrict__ x_param, int n, int off)
{
    const float* x = (X == 1) ? g_y1 : x_param;
    float s[4] = {0, 0, 0, 0}, q[4] = {0, 0, 0, 0};
    int n4 = n * 4;                       // number of float4 elements
    int stride = gridDim.x * 256;
    for (int i = blockIdx.x * 256 + threadIdx.x; i < n4; i += stride) {
        float4 v = reinterpret_cast<const float4*>(x)[i];
        s[0] += v.x; q[0] += v.x * v.x;
        s[1] += v.y; q[1] += v.y * v.y;
        s[2] += v.z; q[2] += v.z * v.z;
        s[3] += v.w; q[3] += v.w * v.w;
    }
#pragma unroll
    for (int d = 4; d < 32; d <<= 1) {
#pragma unroll
        for (int k = 0; k < 4; ++k) {
            s[k] += __shfl_xor_sync(0xFFFFFFFFu, s[k], d);
            q[k] += __shfl_xor_sync(0xFFFFFFFFu, q[k], d);
        }
    }
    int lane = threadIdx.x & 31;
    if (lane < 4) {
        int c0 = lane * 4;               // channel base = (lane%4)*4
#pragma unroll
        for (int k = 0; k < 4; ++k) {
            atomicAdd(&g_stats[off + c0 + k],      s[k]);
            atomicAdd(&g_stats[off + 16 + c0 + k], q[k]);
        }
    }
}

// y = leaky(a[c]*x + b[c] (+ res)).  a,b derived from g_stats per block (16 ch, trivial).
// MODE=1: x=g_y1, out=g_h, no residual.  MODE=2: x=d_out, out=d_out, res=data.
template<int MODE>
__global__ __launch_bounds__(256)
void k_bnact(const float* __restrict__ x_param,
             const float* __restrict__ gamma,
             const float* __restrict__ beta,
             const float* __restrict__ res,     // data for MODE==2, unused for MODE==1
             float*       __restrict__ out_param,
             int n, int off)
{
    __shared__ float sa[16], sb[16];
    if (threadIdx.x < 16) {
        int c = threadIdx.x;
        float inv  = 1.0f / (float)n;
        float mean = g_stats[off + c] * inv;
        float var  = g_stats[off + 16 + c] * inv - mean * mean;
        float a    = gamma[c] * rsqrtf(var + EPS);
        sa[c] = a;
        sb[c] = beta[c] - a * mean;
    }
    __syncthreads();

    const float* x   = (MODE == 1) ? g_y1 : x_param;
    float*       out = (MODE == 1) ? g_h  : out_param;

    int n4 = n * 4;
    int stride = gridDim.x * 256;
    for (int i = blockIdx.x * 256 + threadIdx.x; i < n4; i += stride) {
        float4 v = reinterpret_cast<const float4*>(x)[i];
        int c0 = (i * 4) & 15;
        float4 r = make_float4(0.f, 0.f, 0.f, 0.f);
        if (MODE == 2) r = reinterpret_cast<const float4*>(res)[i];
        v.x = fmaf(v.x, sa[c0 + 0], sb[c0 + 0]) + r.x;  v.x = fmaxf(v.x, SLOPE * v.x);
        v.y = fmaf(v.y, sa[c0 + 1], sb[c0 + 1]) + r.y;  v.y = fmaxf(v.y, SLOPE * v.y);
        v.z = fmaf(v.z, sa[c0 + 2], sb[c0 + 2]) + r.z;  v.z = fmaxf(v.z, SLOPE * v.z);
        v.w = fmaf(v.w, sa[c0 + 3], sb[c0 + 3]) + r.w;  v.w = fmaxf(v.w, SLOPE * v.w);
        reinterpret_cast<float4*>(out)[i] = v;
    }
}

extern "C" void kernel_launch(void* const* d_in, const int* in_sizes, int n_in,
                              void* d_out, int out_size)
{
    const float* data   = (const float*)d_in[0];
    const int*   ind    = (const int*)  d_in[1];
    const float* w1     = (const float*)d_in[2];
    const float* b1     = (const float*)d_in[3];
    const float* gamma1 = (const float*)d_in[4];
    const float* beta1  = (const float*)d_in[5];
    const float* w2     = (const float*)d_in[6];
    const float* gamma2 = (const float*)d_in[7];
    const float* beta2  = (const float*)d_in[8];
    float*       out    = (float*)d_out;

    int n = in_sizes[0] / 16;           // number of nodes
    if (n > NMAX) n = NMAX;

    int conv_blocks = (n + 255) / 256;
    int ew_blocks   = 1184;             // 148 SMs * 8, grid-stride

    k_zero_stats<<<1, 64>>>();
    k_conv<1><<<conv_blocks, 256>>>(data, ind, w1, b1, nullptr, n);
    k_stats<1><<<ew_blocks, 256>>>(nullptr, n, 0);
    k_bnact<1><<<ew_blocks, 256>>>(nullptr, gamma1, beta1, nullptr, nullptr, n, 0);
    k_conv<2><<<conv_blocks, 256>>>(nullptr, ind, w2, nullptr, out, n);
    k_stats<2><<<ew_blocks, 256>>>(out, n, 32);
    k_bnact<2><<<ew_blocks, 256>>>(out, gamma2, beta2, data, out, n, 32);
}